// round 14
// baseline (speedup 1.0000x reference)
#include <cuda_runtime.h>

#define L_SEQ 512
#define T_TAGS 64
#define CHAINS 8          // chains per CTA, 2 warps each
#define THREADS 512
#define PFD 4             // emission prefetch depth (pre-exponentiated)

#define FMA2(d, a, b) asm("fma.rn.f32x2 %0, %1, %2, %0;" : "+l"(d) : "l"(a), "l"(b))
#define ADD2(d, a)    asm("add.rn.f32x2 %0, %0, %1;"      : "+l"(d) : "l"(a))
#define BARC(id)      asm volatile("bar.sync %0, 64;" :: "r"(id) : "memory")

__device__ __forceinline__ unsigned long long pack2(float x, float y) {
    unsigned long long r;
    asm("mov.b64 %0, {%1, %2};" : "=l"(r) : "f"(x), "f"(y));
    return r;
}

__global__ __launch_bounds__(THREADS, 1)
void crf_kernel(const float* __restrict__ logits,
                const unsigned int* __restrict__ tagw,
                const int* __restrict__ mask,
                const float* __restrict__ trans,
                float* __restrict__ out)
{
    // u buffers: 64 floats per chain, double-buffered; 68 pad keeps 16B alignment
    __shared__ __align__(16) float ubuf[2][CHAINS][68];
    __shared__ float red[CHAINS][2][4];     // cross-warp scratch

    const int tid  = threadIdx.x;
    const int w    = tid >> 5;
    const int lane = tid & 31;
    const int c    = w >> 1;            // chain within CTA
    const int h    = w & 1;             // warp-half of the chain
    const int j    = (h << 5) + lane;   // this lane owns tag j (0..63)
    const int barid = c;                // no __syncthreads; ids 0..7 free
    const int b    = blockIdx.x * CHAINS + c;

    // ---- tag dtype detection (int64 LE => odd 32-bit words all zero) ----
    unsigned oddacc = 0;
    #pragma unroll
    for (int k = 0; k < 4; ++k) oddacc |= tagw[2 * (lane + 32 * k) + 1];
    const int is64 = __all_sync(0xffffffffu, oddacc == 0) ? 1 : 0;

    // ---- register cache of exp(trans) column j, packed over i-pairs ----
    // ec[m] = (expT[2m][j], expT[2m+1][j])
    unsigned long long ec[32];
    #pragma unroll
    for (int m = 0; m < 32; ++m) {
        float e0 = __expf(trans[(2 * m) * 64 + j]);
        float e1 = __expf(trans[(2 * m + 1) * 64 + j]);
        ec[m] = pack2(e0, e1);
    }

    const float* lg  = logits + (size_t)b * (L_SEQ * T_TAGS);
    const float* lgj = lg + j;
    const int mbase = b * L_SEQ;

    // ---- gold score prologue (parallel gather): 8 positions per thread ----
    float gp = 0.f;
    int mok = 1;
    #pragma unroll
    for (int k = 0; k < 8; ++k) {
        const int l = j + 64 * k;
        const int mi = mask[mbase + l];
        mok &= (mi == 1);
        const int tg = (int)tagw[is64 ? ((mbase + l) << 1) : (mbase + l)];
        float fm = (float)mi;
        gp += fm * lg[l * T_TAGS + tg];
        if (l > 0) {
            const int tp = (int)tagw[is64 ? ((mbase + l - 1) << 1) : (mbase + l - 1)];
            gp += fm * __ldg(&trans[tp * 64 + tg]);
        }
    }
    mok = __all_sync(0xffffffffu, mok) ? 1 : 0;

    // ---- init: u = exp(alpha0 - alpha0[0]); LR carries the log offset ----
    const float a00 = __ldg(lg);              // alpha0[0], broadcast load
    float mu = __expf(lgj[0] - a00);          // u at tag j
    ubuf[1][c][j] = mu;                       // step 1 reads buf 1
    double lr = (double)a00;

    // ---- emission ring, PRE-EXPONENTIATED: eem[k] = exp(em(step 1+k)) ----
    float eem[PFD];
    #pragma unroll
    for (int k = 0; k < PFD; ++k)
        eem[k] = __expf(__ldg(lgj + (1 + k) * T_TAGS));

    if (lane == 0) red[c][h][0] = (float)mok;
    BARC(barid);                               // publishes ubuf[1] + mok flags
    const bool allones = (red[c][0][0] != 0.f) && (red[c][1][0] != 0.f);

    if (allones) {
        // ======== hot loop: linear space, split chain, 1 bar/step ========
        #pragma unroll 4
        for (int l = 1; l < L_SEQ; ++l) {
            const int slot = (l - 1) & (PFD - 1);
            float f = eem[slot];
            const int lp = (l + PFD < L_SEQ) ? (l + PFD) : (L_SEQ - 1);
            float raw = __ldg(lgj + lp * T_TAGS);   // prefetch emission

            // matvec: s[j] = sum_i u[i] * E[i][j]
            const ulonglong2* pq = (const ulonglong2*)&ubuf[l & 1][c][0];
            unsigned long long A = 0, B = 0, C = 0, D = 0;
            float u0first;
            #pragma unroll
            for (int k = 0; k < 16; ++k) {
                ulonglong2 pp = pq[k];
                if (k == 0) {
                    float dummy;
                    asm("mov.b64 {%0, %1}, %2;" : "=f"(u0first), "=f"(dummy) : "l"(pp.x));
                }
                if (k & 1) { FMA2(C, pp.x, ec[2 * k]); FMA2(D, pp.y, ec[2 * k + 1]); }
                else       { FMA2(A, pp.x, ec[2 * k]); FMA2(B, pp.y, ec[2 * k + 1]); }
            }
            // off-path: refill ring, normalizer, log-carry
            eem[slot] = __expf(raw);
            float r;
            asm("rcp.approx.ftz.f32 %0, %1;" : "=f"(r) : "f"(u0first));
            lr += (double)__logf(u0first);

            ADD2(A, B); ADD2(C, D); ADD2(A, C);
            float slo, shi;
            asm("mov.b64 {%0, %1}, %2;" : "=f"(slo), "=f"(shi) : "l"(A));

            mu = (slo + shi) * (f * r);
            ubuf[(l + 1) & 1][c][j] = mu;
            BARC(barid);
        }
    } else {
        // ======== fallback: with mask select (uniform-scaling exact) ========
        for (int l = 1; l < L_SEQ; ++l) {
            const int slot = (l - 1) & (PFD - 1);
            float f = eem[slot];
            const int lp = (l + PFD < L_SEQ) ? (l + PFD) : (L_SEQ - 1);
            float raw = __ldg(lgj + lp * T_TAGS);
            const int cm = mask[mbase + l];

            const ulonglong2* pq = (const ulonglong2*)&ubuf[l & 1][c][0];
            unsigned long long A = 0, B = 0, C = 0, D = 0;
            float u0first;
            #pragma unroll
            for (int k = 0; k < 16; ++k) {
                ulonglong2 pp = pq[k];
                if (k == 0) {
                    float dummy;
                    asm("mov.b64 {%0, %1}, %2;" : "=f"(u0first), "=f"(dummy) : "l"(pp.x));
                }
                if (k & 1) { FMA2(C, pp.x, ec[2 * k]); FMA2(D, pp.y, ec[2 * k + 1]); }
                else       { FMA2(A, pp.x, ec[2 * k]); FMA2(B, pp.y, ec[2 * k + 1]); }
            }
            eem[slot] = __expf(raw);
            float r;
            asm("rcp.approx.ftz.f32 %0, %1;" : "=f"(r) : "f"(u0first));
            lr += (double)__logf(u0first);

            ADD2(A, B); ADD2(C, D); ADD2(A, C);
            float slo, shi;
            asm("mov.b64 {%0, %1}, %2;" : "=f"(slo), "=f"(shi) : "l"(A));

            float n = (slo + shi) * (f * r);
            // masked step: alpha unchanged => u scaled by uniform r only
            mu = (cm > 0) ? n : mu * r;
            ubuf[(l + 1) & 1][c][j] = mu;
            BARC(barid);
        }
    }

    // ---- epilogue: logZ = LR + log(sum u); subtract gold ----
    float su = mu;
    #pragma unroll
    for (int d = 1; d < 32; d <<= 1)
        su += __shfl_xor_sync(0xffffffffu, su, d);
    #pragma unroll
    for (int d = 1; d < 32; d <<= 1)
        gp += __shfl_xor_sync(0xffffffffu, gp, d);

    if (lane == 0) {
        red[c][h][0] = su;
        red[c][h][1] = gp;
    }
    BARC(barid);

    if (h == 0 && lane == 0) {
        float S = red[c][0][0] + red[c][1][0];
        float G = red[c][0][1] + red[c][1][1];
        out[b] = (float)(lr + (double)__logf(S)) - G;
    }
}

extern "C" void kernel_launch(void* const* d_in, const int* in_sizes, int n_in,
                              void* d_out, int out_size)
{
    const float*        logits = (const float*)d_in[0];
    const unsigned int* tagw   = (const unsigned int*)d_in[1];
    const int*          mask   = (const int*)d_in[2];
    const float*        trans  = (const float*)d_in[3];
    float*              out    = (float*)d_out;

    crf_kernel<<<128, THREADS>>>(logits, tagw, mask, trans, out);
}

// round 15
// speedup vs baseline: 1.1521x; 1.1521x over previous
#include <cuda_runtime.h>

#define L_SEQ 512
#define T_TAGS 64
#define CHAINS 8          // one warp per chain
#define THREADS 256
#define PFD 4             // emission prefetch depth (pre-exponentiated)

#define FMA2(d, a, b) asm("fma.rn.f32x2 %0, %1, %2, %0;" : "+l"(d) : "l"(a), "l"(b))
#define ADD2(d, a)    asm("add.rn.f32x2 %0, %0, %1;"      : "+l"(d) : "l"(a))

__device__ __forceinline__ unsigned long long pack2(float x, float y) {
    unsigned long long r;
    asm("mov.b64 %0, {%1, %2};" : "=l"(r) : "f"(x), "f"(y));
    return r;
}

__global__ __launch_bounds__(THREADS, 1)
void crf_kernel(const float* __restrict__ logits,
                const unsigned int* __restrict__ tagw,
                const int* __restrict__ mask,
                const float* __restrict__ trans,
                float* __restrict__ out)
{
    // u buffers: 64 floats per chain, double-buffered; 68 pad keeps 16B alignment
    __shared__ __align__(16) float ubuf[2][CHAINS][68];

    const int tid  = threadIdx.x;
    const int w    = tid >> 5;          // chain within CTA
    const int lane = tid & 31;
    const int j0   = lane << 1;         // this lane owns tags j0, j0+1
    const int b    = blockIdx.x * CHAINS + w;

    // ---- tag dtype detection (int64 LE => odd 32-bit words all zero) ----
    unsigned oddacc = 0;
    #pragma unroll
    for (int k = 0; k < 4; ++k) oddacc |= tagw[2 * (lane + 32 * k) + 1];
    const int is64 = __all_sync(0xffffffffu, oddacc == 0) ? 1 : 0;

    // ---- register cache of exp(trans): columns j0, j0+1, packed over i-pairs ----
    unsigned long long ec0[32], ec1[32];
    #pragma unroll
    for (int m = 0; m < 32; ++m) {
        float2 ta = *(const float2*)&trans[(2 * m) * 64 + j0];
        float2 tb = *(const float2*)&trans[(2 * m + 1) * 64 + j0];
        ec0[m] = pack2(__expf(ta.x), __expf(tb.x));
        ec1[m] = pack2(__expf(ta.y), __expf(tb.y));
    }

    const float*  lg  = logits + (size_t)b * (L_SEQ * T_TAGS);
    const float2* lg2 = (const float2*)lg;
    const int mbase = b * L_SEQ;

    // ---- gold score prologue (parallel gather): 16 positions per lane ----
    float gp = 0.f;
    int mok = 1;
    #pragma unroll
    for (int k = 0; k < 16; ++k) {
        const int l = lane + 32 * k;
        const int mi = mask[mbase + l];
        mok &= (mi == 1);
        const int tg = (int)tagw[is64 ? ((mbase + l) << 1) : (mbase + l)];
        float fm = (float)mi;
        gp += fm * lg[l * T_TAGS + tg];
        if (l > 0) {
            const int tp = (int)tagw[is64 ? ((mbase + l - 1) << 1) : (mbase + l - 1)];
            gp += fm * __ldg(&trans[tp * 64 + tg]);
        }
    }
    mok = __all_sync(0xffffffffu, mok) ? 1 : 0;

    // ---- init: u = exp(alpha0 - alpha0[0]); lr carries the log offset ----
    const float a00 = __ldg(lg);              // alpha0[0], broadcast load
    float2 alv = lg2[lane];                   // alpha0 at j0, j0+1
    float mu0 = __expf(alv.x - a00);
    float mu1 = __expf(alv.y - a00);
    *(float2*)&ubuf[1][w][j0] = make_float2(mu0, mu1);   // step 1 reads buf 1
    float lr = a00, lrc = 0.f;                // Kahan log-carry

    // ---- emission ring, PRE-EXPONENTIATED: eem[k] = exp(em(step 1+k)) ----
    float2 eem[PFD];
    #pragma unroll
    for (int k = 0; k < PFD; ++k) {
        float2 e = __ldg(&lg2[(1 + k) * 32 + lane]);
        eem[k] = make_float2(__expf(e.x), __expf(e.y));
    }
    __syncwarp();

    if (mok) {
        // ======== hot loop: linear space, software-pipelined LDS batches ========
        #pragma unroll 2
        for (int l = 1; l < L_SEQ; ++l) {
            const int slot = (l - 1) & (PFD - 1);
            float2 f = eem[slot];
            const int lp = (l + PFD < L_SEQ) ? (l + PFD) : (L_SEQ - 1);
            float2 raw = __ldg(&lg2[lp * 32 + lane]);    // prefetch emission

            const ulonglong2* pq = (const ulonglong2*)&ubuf[l & 1][w][0];
            // stage 0: preload batch 0 (pq[0..3])
            ulonglong2 q0 = pq[0], q1 = pq[1], q2 = pq[2], q3 = pq[3];
            float u0first, dumm;
            asm("mov.b64 {%0, %1}, %2;" : "=f"(u0first), "=f"(dumm) : "l"(q0.x));

            unsigned long long A0 = 0, B0 = 0, C0 = 0, D0 = 0;
            unsigned long long A1 = 0, B1 = 0, C1 = 0, D1 = 0;
            #pragma unroll
            for (int t = 0; t < 4; ++t) {
                ulonglong2 n0, n1, n2, n3;
                if (t < 3) {                       // issue next batch's loads early
                    n0 = pq[4 * t + 4]; n1 = pq[4 * t + 5];
                    n2 = pq[4 * t + 6]; n3 = pq[4 * t + 7];
                }
                FMA2(A0, q0.x, ec0[8 * t + 0]); FMA2(A1, q0.x, ec1[8 * t + 0]);
                FMA2(B0, q0.y, ec0[8 * t + 1]); FMA2(B1, q0.y, ec1[8 * t + 1]);
                FMA2(C0, q1.x, ec0[8 * t + 2]); FMA2(C1, q1.x, ec1[8 * t + 2]);
                FMA2(D0, q1.y, ec0[8 * t + 3]); FMA2(D1, q1.y, ec1[8 * t + 3]);
                FMA2(A0, q2.x, ec0[8 * t + 4]); FMA2(A1, q2.x, ec1[8 * t + 4]);
                FMA2(B0, q2.y, ec0[8 * t + 5]); FMA2(B1, q2.y, ec1[8 * t + 5]);
                FMA2(C0, q3.x, ec0[8 * t + 6]); FMA2(C1, q3.x, ec1[8 * t + 6]);
                FMA2(D0, q3.y, ec0[8 * t + 7]); FMA2(D1, q3.y, ec1[8 * t + 7]);
                if (t < 3) { q0 = n0; q1 = n1; q2 = n2; q3 = n3; }
            }

            // off-path: refill ring, normalizer, Kahan log-carry
            eem[slot] = make_float2(__expf(raw.x), __expf(raw.y));
            float r;
            asm("rcp.approx.ftz.f32 %0, %1;" : "=f"(r) : "f"(u0first));
            {
                float tl = __logf(u0first);
                float y = tl - lrc;
                float v = lr + y;
                lrc = (v - lr) - y;
                lr = v;
            }

            ADD2(A0, B0); ADD2(C0, D0); ADD2(A0, C0);
            ADD2(A1, B1); ADD2(C1, D1); ADD2(A1, C1);
            float s0lo, s0hi, s1lo, s1hi;
            asm("mov.b64 {%0, %1}, %2;" : "=f"(s0lo), "=f"(s0hi) : "l"(A0));
            asm("mov.b64 {%0, %1}, %2;" : "=f"(s1lo), "=f"(s1hi) : "l"(A1));

            mu0 = (s0lo + s0hi) * (f.x * r);
            mu1 = (s1lo + s1hi) * (f.y * r);
            *(float2*)&ubuf[(l + 1) & 1][w][j0] = make_float2(mu0, mu1);
            __syncwarp();
        }
    } else {
        // ======== fallback: with mask select (uniform-scaling exact) ========
        for (int l = 1; l < L_SEQ; ++l) {
            const int slot = (l - 1) & (PFD - 1);
            float2 f = eem[slot];
            const int lp = (l + PFD < L_SEQ) ? (l + PFD) : (L_SEQ - 1);
            float2 raw = __ldg(&lg2[lp * 32 + lane]);
            const int cm = mask[mbase + l];

            const ulonglong2* pq = (const ulonglong2*)&ubuf[l & 1][w][0];
            unsigned long long A0 = 0, B0 = 0, C0 = 0, D0 = 0;
            unsigned long long A1 = 0, B1 = 0, C1 = 0, D1 = 0;
            float u0first = 1.f;
            #pragma unroll
            for (int k = 0; k < 16; ++k) {
                ulonglong2 pp = pq[k];
                if (k == 0) {
                    float dummy;
                    asm("mov.b64 {%0, %1}, %2;" : "=f"(u0first), "=f"(dummy) : "l"(pp.x));
                }
                if (k & 1) {
                    FMA2(C0, pp.x, ec0[2 * k]); FMA2(D0, pp.y, ec0[2 * k + 1]);
                    FMA2(C1, pp.x, ec1[2 * k]); FMA2(D1, pp.y, ec1[2 * k + 1]);
                } else {
                    FMA2(A0, pp.x, ec0[2 * k]); FMA2(B0, pp.y, ec0[2 * k + 1]);
                    FMA2(A1, pp.x, ec1[2 * k]); FMA2(B1, pp.y, ec1[2 * k + 1]);
                }
            }
            eem[slot] = make_float2(__expf(raw.x), __expf(raw.y));
            float r;
            asm("rcp.approx.ftz.f32 %0, %1;" : "=f"(r) : "f"(u0first));
            {
                float tl = __logf(u0first);
                float y = tl - lrc;
                float v = lr + y;
                lrc = (v - lr) - y;
                lr = v;
            }

            ADD2(A0, B0); ADD2(C0, D0); ADD2(A0, C0);
            ADD2(A1, B1); ADD2(C1, D1); ADD2(A1, C1);
            float s0lo, s0hi, s1lo, s1hi;
            asm("mov.b64 {%0, %1}, %2;" : "=f"(s0lo), "=f"(s0hi) : "l"(A0));
            asm("mov.b64 {%0, %1}, %2;" : "=f"(s1lo), "=f"(s1hi) : "l"(A1));

            float n0 = (s0lo + s0hi) * (f.x * r);
            float n1 = (s1lo + s1hi) * (f.y * r);
            // masked step: alpha unchanged => u scaled by the uniform r only
            mu0 = (cm > 0) ? n0 : mu0 * r;
            mu1 = (cm > 0) ? n1 : mu1 * r;
            *(float2*)&ubuf[(l + 1) & 1][w][j0] = make_float2(mu0, mu1);
            __syncwarp();
        }
    }

    // ---- epilogue: logZ = lr + log(sum u); subtract gold ----
    float su = mu0 + mu1;
    #pragma unroll
    for (int d = 1; d < 32; d <<= 1)
        su += __shfl_xor_sync(0xffffffffu, su, d);
    #pragma unroll
    for (int d = 1; d < 32; d <<= 1)
        gp += __shfl_xor_sync(0xffffffffu, gp, d);

    if (lane == 0)
        out[b] = (lr + (__logf(su) - lrc)) - gp;
}

extern "C" void kernel_launch(void* const* d_in, const int* in_sizes, int n_in,
                              void* d_out, int out_size)
{
    const float*        logits = (const float*)d_in[0];
    const unsigned int* tagw   = (const unsigned int*)d_in[1];
    const int*          mask   = (const int*)d_in[2];
    const float*        trans  = (const float*)d_in[3];
    float*              out    = (float*)d_out;

    crf_kernel<<<128, THREADS>>>(logits, tagw, mask, trans, out);
}